// round 1
// baseline (speedup 1.0000x reference)
#include <cuda_runtime.h>
#include <cstdint>

// ---------------------------------------------------------------------------
// VersorLinear (Cl(4,1) geometric linear layer, 32-dim algebra)
//
//   y[b,o,k] = sum_{f,i} x[b,f,i] * W[o,f,i^k] * s(i, i^k)
//   y <- y * rsqrt(sum_k y^2 + 1e-6)
//
// Reduced to: Y = X @ Wc, where
//   X  : [4096, 4096]   (b, f*32+i)  row-major (native layout of x)
//   Wc : [4096, 4096]   (f*32+i, o*32+k), Wc = W[o,f,i^k] * cayley_sign(i, i^k)
//   Y  : [4096, 4096]   (b, o*32+k) row-major (native layout of y)
// Normalization fused into the GEMM epilogue (32-col k-groups live in a
// 4-lane quad of the thread tile -> shfl_xor reduction).
// ---------------------------------------------------------------------------

#define MDIM 4096
#define NDIM 4096
#define KDIM 4096

// 64 MB folded-weight scratch (static device global; no runtime allocation)
__device__ float g_Wc[(size_t)KDIM * NDIM];

// Cayley sign for e_a * e_b in Cl(4,1), SIG = [1,1,1,1,-1]
__device__ __forceinline__ float cayley_sign(int a, int b) {
    int s = 0;
    int aa = a >> 1;
    while (aa) {            // reorder parity: move b's generators past a's
        s += __popc(aa & b);
        aa >>= 1;
    }
    s += ((a & b) >> 4) & 1;  // metric: generator 4 squares to -1
    return (s & 1) ? -1.0f : 1.0f;
}

// ---------------------------------------------------------------------------
// Fold kernel: Wc[(f*32+i)*4096 + (o*32+k)] = W[o*4096 + f*32 + (i^k)] * sign
// W layout: [OUT_F=128, IN_F=128, GA=32] row-major.
// ---------------------------------------------------------------------------
__global__ void fold_kernel(const float* __restrict__ W) {
    int idx = blockIdx.x * blockDim.x + threadIdx.x;  // 0 .. 16777215
    int n  = idx & (NDIM - 1);   // o*32 + k
    int kk = idx >> 12;          // f*32 + i
    int i = kk & 31;
    int f = kk >> 5;
    int k = n & 31;
    int o = n >> 5;
    int j = i ^ k;
    float s = cayley_sign(i, j);
    g_Wc[idx] = W[(o << 12) + (f << 5) + j] * s;
}

// ---------------------------------------------------------------------------
// Tiled fp32 GEMM: C = A @ g_Wc, 128x128 block tile, BK=8, 8x8 per thread.
// Fused epilogue: per-(row, 32-col group) L2 normalization.
// ---------------------------------------------------------------------------
__global__ __launch_bounds__(256, 2)
void gemm_norm_kernel(const float* __restrict__ A, float* __restrict__ C) {
    constexpr int BM = 128, BN = 128, BK = 8, TM = 8, TN = 8;

    __shared__ float As[BK][BM];   // transposed A tile
    __shared__ float Bs[BK][BN];

    const int tid = threadIdx.x;                 // 0..255
    const int blockRow = blockIdx.y * BM;
    const int blockCol = blockIdx.x * BN;

    // 16x16 thread grid over the 128x128 tile
    const int tRow = (tid >> 4) * TM;
    const int tCol = (tid & 15) * TN;

    // Global load assignments (one float4 each per BK step)
    const int aRow = tid >> 1;             // 0..127
    const int aCol = (tid & 1) * 4;        // 0 or 4
    const int bRow = tid >> 5;             // 0..7
    const int bCol = (tid & 31) * 4;       // 0..124

    const float* Aptr = A + (size_t)(blockRow + aRow) * KDIM + aCol;
    const float* Bptr = g_Wc + (size_t)bRow * NDIM + blockCol + bCol;

    float acc[TM][TN] = {};
    float regM[TM], regN[TN];

    for (int k0 = 0; k0 < KDIM; k0 += BK) {
        float4 a4 = *reinterpret_cast<const float4*>(Aptr);
        float4 b4 = *reinterpret_cast<const float4*>(Bptr);

        As[aCol + 0][aRow] = a4.x;
        As[aCol + 1][aRow] = a4.y;
        As[aCol + 2][aRow] = a4.z;
        As[aCol + 3][aRow] = a4.w;
        *reinterpret_cast<float4*>(&Bs[bRow][bCol]) = b4;
        __syncthreads();

#pragma unroll
        for (int kk = 0; kk < BK; kk++) {
#pragma unroll
            for (int m = 0; m < TM; m++) regM[m] = As[kk][tRow + m];
#pragma unroll
            for (int n = 0; n < TN; n++) regN[n] = Bs[kk][tCol + n];
#pragma unroll
            for (int m = 0; m < TM; m++)
#pragma unroll
                for (int n = 0; n < TN; n++)
                    acc[m][n] += regM[m] * regN[n];
        }
        __syncthreads();

        Aptr += BK;
        Bptr += (size_t)BK * NDIM;
    }

    // ---- fused manifold normalization + store ----
    // Each 32-column k-group (fixed b, fixed o) spans 4 adjacent lanes
    // (tid&15 in {4g..4g+3}) at the same tRow. shfl_xor(1|2) stays inside
    // that quad (bit 4 of the lane id carries tRow, untouched).
#pragma unroll
    for (int m = 0; m < TM; m++) {
        float ss = 0.f;
#pragma unroll
        for (int n = 0; n < TN; n++) ss += acc[m][n] * acc[m][n];
        ss += __shfl_xor_sync(0xffffffffu, ss, 1);
        ss += __shfl_xor_sync(0xffffffffu, ss, 2);
        float inv = rsqrtf(ss + 1e-6f);

        float* crow = C + (size_t)(blockRow + tRow + m) * NDIM + blockCol + tCol;
        float4 v0 = make_float4(acc[m][0] * inv, acc[m][1] * inv,
                                acc[m][2] * inv, acc[m][3] * inv);
        float4 v1 = make_float4(acc[m][4] * inv, acc[m][5] * inv,
                                acc[m][6] * inv, acc[m][7] * inv);
        *reinterpret_cast<float4*>(crow)     = v0;
        *reinterpret_cast<float4*>(crow + 4) = v1;
    }
}

// ---------------------------------------------------------------------------
extern "C" void kernel_launch(void* const* d_in, const int* in_sizes, int n_in,
                              void* d_out, int out_size) {
    // x: [4096,128,32] (16,777,216 elems), weight: [128,128,32] (524,288 elems)
    const float* x = (const float*)d_in[0];
    const float* w = (const float*)d_in[1];
    if (n_in >= 2 && in_sizes[0] == 524288 && in_sizes[1] == 16777216) {
        // defensive: swap if metadata order differs
        const float* t = x; x = w; w = t;
    }
    float* y = (float*)d_out;

    fold_kernel<<<65536, 256>>>(w);

    dim3 grid(NDIM / 128, MDIM / 128);  // 32 x 32
    gemm_norm_kernel<<<grid, 256>>>(x, y);
}

// round 2
// speedup vs baseline: 3.9147x; 3.9147x over previous
#include <cuda_runtime.h>
#include <cstdint>

// ---------------------------------------------------------------------------
// VersorLinear (Cl(4,1), 32-dim algebra) == one 4096^3 GEMM + fused L2 norm.
//   Y[b, o*32+k] = sum_{f,i} X[b, f*32+i] * Wc[f*32+i, o*32+k]
//   Wc[(f,i),(o,k)] = W[o,f,i^k] * cayley_sign(i, i^k)
// TF32 tensor cores (mma.sync.m16n8k8), cp.async double buffer, folded weight
// stored TRANSPOSED ([n][k]) and pre-rounded to tf32 so A- and B-tile paths
// are symmetric and fragment LDS is conflict-free (stride 36).
// ---------------------------------------------------------------------------

#define MDIM 4096
#define NDIM 4096
#define KDIM 4096

// 64 MB folded/transposed weight: g_Wt[n][k]  (n = o*32+k_blade, k = f*32+i)
__device__ float g_Wt[(size_t)NDIM * KDIM];

__device__ __forceinline__ float cayley_sign(int a, int b) {
    int s = 0;
    int aa = a >> 1;
    while (aa) {            // reorder parity
        s += __popc(aa & b);
        aa >>= 1;
    }
    s += ((a & b) >> 4) & 1;  // e4^2 = -1 (SIG=[1,1,1,1,-1])
    return (s & 1) ? -1.0f : 1.0f;
}

// Fold: g_Wt[n*4096 + kk] = tf32(W[o,f,i^k] * sign), n=o*32+k, kk=f*32+i
__global__ void fold_kernel(const float* __restrict__ W) {
    int idx = blockIdx.x * blockDim.x + threadIdx.x;
    int kk = idx & (KDIM - 1);
    int n  = idx >> 12;
    int i = kk & 31, f = kk >> 5, k = n & 31, o = n >> 5;
    int j = i ^ k;
    float v = W[(o << 12) + (f << 5) + j] * cayley_sign(i, j);
    uint32_t u;
    asm("cvt.rna.tf32.f32 %0, %1;" : "=r"(u) : "f"(v));
    g_Wt[idx] = __uint_as_float(u);
}

// ---------------------------------------------------------------------------
#define BM 128
#define BN 128
#define BK 32
#define LDSD 36   // smem row stride (floats): conflict-free for frag loads

#define CP_ASYNC16(smaddr, gptr) \
    asm volatile("cp.async.cg.shared.global [%0], [%1], 16;" :: "r"(smaddr), "l"(gptr))

#define CVT_TF32(u, f) asm("cvt.rna.tf32.f32 %0, %1;" : "=r"(u) : "f"(f))

__global__ __launch_bounds__(256, 2)
void gemm_tc_kernel(const float* __restrict__ A, float* __restrict__ C) {
    extern __shared__ float smem[];
    float* As = smem;                    // [2][BM][LDSD]
    float* Bs = smem + 2 * BM * LDSD;    // [2][BN][LDSD]
    uint32_t sAs = (uint32_t)__cvta_generic_to_shared(As);
    uint32_t sBs = (uint32_t)__cvta_generic_to_shared(Bs);

    const int tid  = threadIdx.x;
    const int lane = tid & 31;
    const int wid  = tid >> 5;
    const int warpM = wid >> 2;          // 0..1  -> 64-row warp tile
    const int warpN = wid & 3;           // 0..3  -> 32-col warp tile
    const int blockRow = blockIdx.y * BM;
    const int blockCol = blockIdx.x * BN;

    // gmem->smem: 4 float4 per thread per matrix per tile
    const int r0 = tid >> 3;             // 0..31 (each it adds 32 rows)
    const int c4 = (tid & 7) * 4;        // 0..28
    const float* gA = A    + (size_t)(blockRow + r0) * KDIM + c4;
    const float* gB = g_Wt + (size_t)(blockCol + r0) * KDIM + c4;

#define LOAD_TILE(t, stage) do {                                               \
    const float* _ga = gA + (size_t)(t) * BK;                                  \
    const float* _gb = gB + (size_t)(t) * BK;                                  \
    uint32_t _sa = sAs + (uint32_t)(((stage) * BM + r0) * LDSD + c4) * 4u;     \
    uint32_t _sb = sBs + (uint32_t)(((stage) * BN + r0) * LDSD + c4) * 4u;     \
    _Pragma("unroll")                                                          \
    for (int _it = 0; _it < 4; _it++) {                                        \
        CP_ASYNC16(_sa + _it * 32 * LDSD * 4, _ga + (size_t)_it * 32 * KDIM);  \
        CP_ASYNC16(_sb + _it * 32 * LDSD * 4, _gb + (size_t)_it * 32 * KDIM);  \
    }                                                                          \
    asm volatile("cp.async.commit_group;");                                    \
} while (0)

    float acc[4][4][4] = {};             // [mf][nf][c0..c3]

    LOAD_TILE(0, 0);

    const int T = KDIM / BK;             // 128
    for (int t = 0; t < T; t++) {
        const int stage = t & 1;
        if (t + 1 < T) {
            LOAD_TILE(t + 1, (t + 1) & 1);
            asm volatile("cp.async.wait_group 1;");
        } else {
            asm volatile("cp.async.wait_group 0;");
        }
        __syncthreads();

        const float* as = As + stage * BM * LDSD
                        + (warpM * 64 + (lane >> 2)) * LDSD + (lane & 3);
        const float* bs = Bs + stage * BN * LDSD
                        + (warpN * 32 + (lane >> 2)) * LDSD + (lane & 3);

#pragma unroll
        for (int ks = 0; ks < 4; ks++) {
            const int kof = ks * 8;
            uint32_t a[4][4], b[4][2];
#pragma unroll
            for (int mf = 0; mf < 4; mf++) {
                float f0 = as[(mf * 16    ) * LDSD + kof    ];   // (g,   t)
                float f1 = as[(mf * 16 + 8) * LDSD + kof    ];   // (g+8, t)
                float f2 = as[(mf * 16    ) * LDSD + kof + 4];   // (g,   t+4)
                float f3 = as[(mf * 16 + 8) * LDSD + kof + 4];   // (g+8, t+4)
                CVT_TF32(a[mf][0], f0);
                CVT_TF32(a[mf][1], f1);
                CVT_TF32(a[mf][2], f2);
                CVT_TF32(a[mf][3], f3);
            }
#pragma unroll
            for (int nf = 0; nf < 4; nf++) {
                // Bs holds pre-rounded tf32 bits already
                b[nf][0] = __float_as_uint(bs[(nf * 8) * LDSD + kof    ]);
                b[nf][1] = __float_as_uint(bs[(nf * 8) * LDSD + kof + 4]);
            }
#pragma unroll
            for (int mf = 0; mf < 4; mf++)
#pragma unroll
                for (int nf = 0; nf < 4; nf++)
                    asm volatile(
                        "mma.sync.aligned.m16n8k8.row.col.f32.tf32.tf32.f32 "
                        "{%0,%1,%2,%3}, {%4,%5,%6,%7}, {%8,%9}, {%0,%1,%2,%3};"
                        : "+f"(acc[mf][nf][0]), "+f"(acc[mf][nf][1]),
                          "+f"(acc[mf][nf][2]), "+f"(acc[mf][nf][3])
                        : "r"(a[mf][0]), "r"(a[mf][1]), "r"(a[mf][2]), "r"(a[mf][3]),
                          "r"(b[nf][0]), "r"(b[nf][1]));
        }
        __syncthreads();
    }

    // ---- fused manifold normalization + store ----
    // Each warp's 32 output columns are exactly one blade group (o fixed);
    // row r's 32 columns live in the lane quad sharing (lane>>2).
#pragma unroll
    for (int mf = 0; mf < 4; mf++) {
        float slo = 0.f, shi = 0.f;
#pragma unroll
        for (int nf = 0; nf < 4; nf++) {
            slo += acc[mf][nf][0] * acc[mf][nf][0] + acc[mf][nf][1] * acc[mf][nf][1];
            shi += acc[mf][nf][2] * acc[mf][nf][2] + acc[mf][nf][3] * acc[mf][nf][3];
        }
        slo += __shfl_xor_sync(0xffffffffu, slo, 1);
        slo += __shfl_xor_sync(0xffffffffu, slo, 2);
        shi += __shfl_xor_sync(0xffffffffu, shi, 1);
        shi += __shfl_xor_sync(0xffffffffu, shi, 2);
        float ilo = rsqrtf(slo + 1e-6f);
        float ihi = rsqrtf(shi + 1e-6f);

        int rlo  = blockRow + warpM * 64 + mf * 16 + (lane >> 2);
        int col0 = blockCol + warpN * 32 + (lane & 3) * 2;
#pragma unroll
        for (int nf = 0; nf < 4; nf++) {
            float2 vlo = make_float2(acc[mf][nf][0] * ilo, acc[mf][nf][1] * ilo);
            float2 vhi = make_float2(acc[mf][nf][2] * ihi, acc[mf][nf][3] * ihi);
            *reinterpret_cast<float2*>(C + (size_t)rlo * NDIM + col0 + nf * 8) = vlo;
            *reinterpret_cast<float2*>(C + (size_t)(rlo + 8) * NDIM + col0 + nf * 8) = vhi;
        }
    }
}

// ---------------------------------------------------------------------------
extern "C" void kernel_launch(void* const* d_in, const int* in_sizes, int n_in,
                              void* d_out, int out_size) {
    const float* x = (const float*)d_in[0];
    const float* w = (const float*)d_in[1];
    if (n_in >= 2 && in_sizes[0] == 524288 && in_sizes[1] == 16777216) {
        const float* t = x; x = w; w = t;  // defensive order swap
    }
    float* y = (float*)d_out;

    fold_kernel<<<65536, 256>>>(w);  // 16,777,216 elements

    const int smem_bytes = 2 * (BM + BN) * LDSD * (int)sizeof(float);  // 73728
    cudaFuncSetAttribute(gemm_tc_kernel,
                         cudaFuncAttributeMaxDynamicSharedMemorySize, smem_bytes);
    dim3 grid(NDIM / BN, MDIM / BM);  // 32 x 32
    gemm_tc_kernel<<<grid, 256, smem_bytes>>>(x, y);
}

// round 4
// speedup vs baseline: 4.3611x; 1.1140x over previous
#include <cuda_runtime.h>
#include <cstdint>

// ---------------------------------------------------------------------------
// VersorLinear (Cl(4,1), 32-dim algebra) == one 4096^3 GEMM + fused L2 norm.
//   Y[b, o*32+k] = sum_{f,i} X[b, f*32+i] * Wc[f*32+i, o*32+k]
//   Wc[(f,i),(o,k)] = W[o,f,i^k] * cayley_sign(i, i^k)
// Round 4: classic mma.sync.m16n8k8.tf32 (target sm_103 baseline — tcgen05 is
// rejected by ptxas at this target), issue-optimized:
//   - 64x64 warp tile (32 MMA per 32 LDS per k-slice)
//   - no per-fragment cvt (raw fp32 bits -> HW tf32 truncation; bias cancels
//     under the fused normalization)
//   - 3-stage cp.async pipeline, 128 threads/CTA, 2 CTAs/SM
// ---------------------------------------------------------------------------

#define MDIM 4096
#define NDIM 4096
#define KDIM 4096

// 64 MB folded/transposed weight: g_Wt[n][k]  (n = o*32+k_blade, k = f*32+i)
__device__ float g_Wt[(size_t)NDIM * KDIM];

__device__ __forceinline__ float cayley_sign(int a, int b) {
    int s = 0;
    int aa = a >> 1;
    while (aa) {            // reorder parity
        s += __popc(aa & b);
        aa >>= 1;
    }
    s += ((a & b) >> 4) & 1;  // e4^2 = -1 (SIG=[1,1,1,1,-1])
    return (s & 1) ? -1.0f : 1.0f;
}

// g_Wt[n*4096 + kk] = tf32_rna(W[o,f,i^k] * sign), n=o*32+k, kk=f*32+i
__global__ void fold_kernel(const float* __restrict__ W) {
    int idx = blockIdx.x * blockDim.x + threadIdx.x;
    int kk = idx & (KDIM - 1);
    int n  = idx >> 12;
    int i = kk & 31, f = kk >> 5, k = n & 31, o = n >> 5;
    int j = i ^ k;
    float v = W[(o << 12) + (f << 5) + j] * cayley_sign(i, j);
    uint32_t u;
    asm("cvt.rna.tf32.f32 %0, %1;" : "=r"(u) : "f"(v));
    g_Wt[idx] = __uint_as_float(u);
}

// ---------------------------------------------------------------------------
#define BM 128
#define BN 128
#define BK 32
#define NST 3
#define LDSD 36                         // smem row stride (floats)
#define STG_F (BM * LDSD)               // floats per stage per matrix (4608)

#define CP_ASYNC16(smaddr, gptr) \
    asm volatile("cp.async.cg.shared.global [%0], [%1], 16;" :: "r"(smaddr), "l"(gptr))

__global__ __launch_bounds__(128, 2)
void gemm_tc_kernel(const float* __restrict__ A, float* __restrict__ C) {
    extern __shared__ float smem[];
    float* As = smem;                    // [NST][BM][LDSD]
    float* Bs = smem + NST * STG_F;      // [NST][BN][LDSD]
    uint32_t sAs = (uint32_t)__cvta_generic_to_shared(As);
    uint32_t sBs = (uint32_t)__cvta_generic_to_shared(Bs);

    const int tid  = threadIdx.x;        // 0..127
    const int lane = tid & 31;
    const int wid  = tid >> 5;           // 0..3
    const int warpM = wid >> 1;          // 0..1 -> 64-row warp tile
    const int warpN = wid & 1;           // 0..1 -> 64-col warp tile
    const int blockRow = blockIdx.y * BM;
    const int blockCol = blockIdx.x * BN;

    // gmem->smem: 8 float4 per thread per matrix per stage
    const int r0 = tid >> 3;             // 0..15 (each i adds 16 rows)
    const int c4 = (tid & 7) * 4;        // 0..28
    const float* gA = A    + (size_t)(blockRow + r0) * KDIM + c4;
    const float* gB = g_Wt + (size_t)(blockCol + r0) * KDIM + c4;

#define LOAD_TILE(t, stage) do {                                               \
    const float* _ga = gA + (size_t)(t) * BK;                                  \
    const float* _gb = gB + (size_t)(t) * BK;                                  \
    uint32_t _sa = sAs + (uint32_t)((stage) * STG_F + r0 * LDSD + c4) * 4u;    \
    uint32_t _sb = sBs + (uint32_t)((stage) * STG_F + r0 * LDSD + c4) * 4u;    \
    _Pragma("unroll")                                                          \
    for (int _it = 0; _it < 8; _it++) {                                        \
        CP_ASYNC16(_sa + _it * 16 * LDSD * 4, _ga + (size_t)_it * 16 * KDIM);  \
        CP_ASYNC16(_sb + _it * 16 * LDSD * 4, _gb + (size_t)_it * 16 * KDIM);  \
    }                                                                          \
    asm volatile("cp.async.commit_group;");                                    \
} while (0)

    float acc[4][8][4] = {};             // [mf][nf][c0..c3]

    LOAD_TILE(0, 0);
    LOAD_TILE(1, 1);

    const int T = KDIM / BK;             // 128
    for (int t = 0; t < T; t++) {
        const int stage = t % NST;
        if (t < T - 1) asm volatile("cp.async.wait_group 1;");
        else           asm volatile("cp.async.wait_group 0;");
        __syncthreads();
        if (t + 2 < T) LOAD_TILE(t + 2, (t + 2) % NST);

        const float* as = As + stage * STG_F
                        + (warpM * 64 + (lane >> 2)) * LDSD + (lane & 3);
        const float* bs = Bs + stage * STG_F
                        + (warpN * 64 + (lane >> 2)) * LDSD + (lane & 3);

#pragma unroll
        for (int ks = 0; ks < 4; ks++) {
            const int kof = ks * 8;
            uint32_t a[4][4], b[8][2];
#pragma unroll
            for (int mf = 0; mf < 4; mf++) {
                // raw fp32 bits: HW truncates to tf32 inside the MMA
                a[mf][0] = __float_as_uint(as[(mf * 16    ) * LDSD + kof    ]);
                a[mf][1] = __float_as_uint(as[(mf * 16 + 8) * LDSD + kof    ]);
                a[mf][2] = __float_as_uint(as[(mf * 16    ) * LDSD + kof + 4]);
                a[mf][3] = __float_as_uint(as[(mf * 16 + 8) * LDSD + kof + 4]);
            }
#pragma unroll
            for (int nf = 0; nf < 8; nf++) {
                b[nf][0] = __float_as_uint(bs[(nf * 8) * LDSD + kof    ]);
                b[nf][1] = __float_as_uint(bs[(nf * 8) * LDSD + kof + 4]);
            }
#pragma unroll
            for (int mf = 0; mf < 4; mf++)
#pragma unroll
                for (int nf = 0; nf < 8; nf++)
                    asm volatile(
                        "mma.sync.aligned.m16n8k8.row.col.f32.tf32.tf32.f32 "
                        "{%0,%1,%2,%3}, {%4,%5,%6,%7}, {%8,%9}, {%0,%1,%2,%3};"
                        : "+f"(acc[mf][nf][0]), "+f"(acc[mf][nf][1]),
                          "+f"(acc[mf][nf][2]), "+f"(acc[mf][nf][3])
                        : "r"(a[mf][0]), "r"(a[mf][1]), "r"(a[mf][2]), "r"(a[mf][3]),
                          "r"(b[nf][0]), "r"(b[nf][1]));
        }
        __syncthreads();
    }

    // ---- fused manifold normalization + store ----
    // Warp tile cols [warpN*64, warpN*64+64) = two 32-col blade groups:
    // nf 0..3 -> group A, nf 4..7 -> group B. Row r's group values live in
    // the lane quad sharing (lane>>2): shfl_xor(1|2) reduces within it.
#pragma unroll
    for (int mf = 0; mf < 4; mf++) {
        float sA0 = 0.f, sA1 = 0.f, sB0 = 0.f, sB1 = 0.f;
#pragma unroll
        for (int nf = 0; nf < 4; nf++) {
            sA0 += acc[mf][nf][0] * acc[mf][nf][0] + acc[mf][nf][1] * acc[mf][nf][1];
            sA1 += acc[mf][nf][2] * acc[mf][nf][2] + acc[mf][nf][3] * acc[mf][nf][3];
            sB0 += acc[mf][nf+4][0] * acc[mf][nf+4][0] + acc[mf][nf+4][1] * acc[mf][nf+4][1];
            sB1 += acc[mf][nf+4][2] * acc[mf][nf+4][2] + acc[mf][nf+4][3] * acc[mf][nf+4][3];
        }
        sA0 += __shfl_xor_sync(0xffffffffu, sA0, 1);
        sA0 += __shfl_xor_sync(0xffffffffu, sA0, 2);
        sA1 += __shfl_xor_sync(0xffffffffu, sA1, 1);
        sA1 += __shfl_xor_sync(0xffffffffu, sA1, 2);
        sB0 += __shfl_xor_sync(0xffffffffu, sB0, 1);
        sB0 += __shfl_xor_sync(0xffffffffu, sB0, 2);
        sB1 += __shfl_xor_sync(0xffffffffu, sB1, 1);
        sB1 += __shfl_xor_sync(0xffffffffu, sB1, 2);
        float iA0 = rsqrtf(sA0 + 1e-6f), iA1 = rsqrtf(sA1 + 1e-6f);
        float iB0 = rsqrtf(sB0 + 1e-6f), iB1 = rsqrtf(sB1 + 1e-6f);

        int rlo  = blockRow + warpM * 64 + mf * 16 + (lane >> 2);
        int col0 = blockCol + warpN * 64 + (lane & 3) * 2;
#pragma unroll
        for (int nf = 0; nf < 8; nf++) {
            float i0 = (nf < 4) ? iA0 : iB0;
            float i1 = (nf < 4) ? iA1 : iB1;
            *reinterpret_cast<float2*>(C + (size_t)rlo * NDIM + col0 + nf * 8) =
                make_float2(acc[mf][nf][0] * i0, acc[mf][nf][1] * i0);
            *reinterpret_cast<float2*>(C + (size_t)(rlo + 8) * NDIM + col0 + nf * 8) =
                make_float2(acc[mf][nf][2] * i1, acc[mf][nf][3] * i1);
        }
    }
}

// ---------------------------------------------------------------------------
extern "C" void kernel_launch(void* const* d_in, const int* in_sizes, int n_in,
                              void* d_out, int out_size) {
    const float* x = (const float*)d_in[0];
    const float* w = (const float*)d_in[1];
    if (n_in >= 2 && in_sizes[0] == 524288 && in_sizes[1] == 16777216) {
        const float* t = x; x = w; w = t;  // defensive order swap
    }
    float* y = (float*)d_out;

    fold_kernel<<<65536, 256>>>(w);  // 16,777,216 elements

    const int smem_bytes = NST * 2 * STG_F * (int)sizeof(float);  // 110592
    cudaFuncSetAttribute(gemm_tc_kernel,
                         cudaFuncAttributeMaxDynamicSharedMemorySize, smem_bytes);
    dim3 grid(NDIM / BN, MDIM / BM);  // 32 x 32
    gemm_tc_kernel<<<grid, 128, smem_bytes>>>(x, y);
}